// round 7
// baseline (speedup 1.0000x reference)
#include <cuda_runtime.h>

#define CH   64
#define HH   112
#define WW   112
#define HWS  12544
#define BB   4
#define KK   49
#define NPIX (BB*HWS)

// Scratch (device globals — no allocation allowed). Zero-initialized at load.
__device__ __align__(16) float g_y0  [BB*CH*HWS];   // reduce output (pre-BN1)
__device__ __align__(16) float g_out0[BB*CH*HWS];   // involution output (pre-BN2)
__device__ float g_stats1[2*CH];
__device__ float g_stats2[2*CH];

// ---------------------------------------------------------------- K1: reduce GEMM + stats1
// y0[b,o,p] = sum_c wred[o,c]*x[b,c,p]. Block: 128 pixels, 256 threads, 8o x 4pix tiles.
// (Exact R2 shape — best measured. Block (0,0) zeroes g_stats2 for this replay.)
__global__ __launch_bounds__(256) void k_reduce(const float* __restrict__ x,
                                                const float* __restrict__ wred) {
    __shared__ __align__(16) float xs[CH][128];
    __shared__ float ws[CH][CH];
    const int t = threadIdx.x;
    const int b = blockIdx.y;
    const int pix0 = blockIdx.x * 128;

    if (blockIdx.x == 0 && blockIdx.y == 0 && t < 2*CH) g_stats2[t] = 0.f;

    const float* xb = x + (size_t)b*CH*HWS + pix0;
    for (int l = t; l < CH*128; l += 256) {
        int c = l >> 7, p = l & 127;
        xs[c][p] = xb[(size_t)c*HWS + p];
    }
    for (int l = t; l < CH*CH; l += 256) ws[l >> 6][l & 63] = wred[l];
    __syncthreads();

    const int og = t >> 5;
    const int pg = t & 31;
    float acc[8][4];
    #pragma unroll
    for (int i = 0; i < 8; i++)
        #pragma unroll
        for (int j = 0; j < 4; j++) acc[i][j] = 0.f;

    #pragma unroll 4
    for (int c = 0; c < CH; c++) {
        float4 xv = ((const float4*)xs[c])[pg];
        #pragma unroll
        for (int i = 0; i < 8; i++) {
            float w = ws[og*8 + i][c];
            acc[i][0] = fmaf(w, xv.x, acc[i][0]);
            acc[i][1] = fmaf(w, xv.y, acc[i][1]);
            acc[i][2] = fmaf(w, xv.z, acc[i][2]);
            acc[i][3] = fmaf(w, xv.w, acc[i][3]);
        }
    }

    float* y0b = g_y0 + (size_t)b*CH*HWS + pix0;
    #pragma unroll
    for (int i = 0; i < 8; i++) {
        const int o = og*8 + i;
        float4 v; v.x = acc[i][0]; v.y = acc[i][1]; v.z = acc[i][2]; v.w = acc[i][3];
        ((float4*)(y0b + (size_t)o*HWS))[pg] = v;
        float s = v.x + v.y + v.z + v.w;
        float q = v.x*v.x + v.y*v.y + v.z*v.z + v.w*v.w;
        #pragma unroll
        for (int off = 16; off; off >>= 1) {
            s += __shfl_down_sync(0xffffffffu, s, off);
            q += __shfl_down_sync(0xffffffffu, q, off);
        }
        if (pg == 0) {
            atomicAdd(&g_stats1[o], s);
            atomicAdd(&g_stats1[CH + o], q);
        }
    }
}

// ---------------------------------------------------------------- K2: bn1 + span GEMM + involution + stats2
// (Exact R2 shape — 128-pixel tiles, per-pixel kernels live only in smem.)
__global__ __launch_bounds__(256, 3) void k_main(const float* __restrict__ x,
                                                 const float* __restrict__ wspan,
                                                 const float* __restrict__ g1,
                                                 const float* __restrict__ b1) {
    extern __shared__ __align__(16) float sm[];
    float* ws   = sm;                       // [49*64]  span weights
    float* ys   = ws + KK*CH;               // [64*128] bn1-relu'd y0 tile
    float* ks   = ys + CH*128;              // [49*128] per-pixel kernels
    float* bn   = ks + KK*128;              // [128]    bn1 scale/shift
    float* sred = bn + 128;                 // [128]    stats2 partial

    const int t = threadIdx.x;
    const int b = blockIdx.y;
    const int pix0 = blockIdx.x * 128;

    if (t < CH) {
        const float n = (float)NPIX;
        float mean = g_stats1[t] / n;
        float var  = g_stats1[CH + t] / n - mean*mean;
        float sc = g1[t] * rsqrtf(var + 1e-5f);
        bn[t]      = sc;
        bn[CH + t] = b1[t] - mean*sc;
    }
    if (t < 128) sred[t] = 0.f;
    for (int l = t; l < KK*CH; l += 256) ws[l] = wspan[l];
    __syncthreads();

    const float* y0b = g_y0 + (size_t)b*CH*HWS + pix0;
    for (int l = t; l < CH*128; l += 256) {
        int c = l >> 7, p = l & 127;
        float v = y0b[(size_t)c*HWS + p];
        ys[l] = fmaxf(fmaf(v, bn[c], bn[CH + c]), 0.f);
    }
    __syncthreads();

    // ---- span GEMM: ks[p][pix] = sum_c ws[p][c]*ys[c][pix] (warps 0..6) ----
    {
        const int og = t >> 5;
        const int pg = t & 31;
        if (og < 7) {
            float acc[7][4];
            #pragma unroll
            for (int i = 0; i < 7; i++)
                #pragma unroll
                for (int j = 0; j < 4; j++) acc[i][j] = 0.f;
            #pragma unroll 4
            for (int c = 0; c < CH; c++) {
                float4 xv = ((const float4*)(ys + c*128))[pg];
                #pragma unroll
                for (int i = 0; i < 7; i++) {
                    float w = ws[(og*7 + i)*CH + c];
                    acc[i][0] = fmaf(w, xv.x, acc[i][0]);
                    acc[i][1] = fmaf(w, xv.y, acc[i][1]);
                    acc[i][2] = fmaf(w, xv.z, acc[i][2]);
                    acc[i][3] = fmaf(w, xv.w, acc[i][3]);
                }
            }
            #pragma unroll
            for (int i = 0; i < 7; i++) {
                float4 v; v.x = acc[i][0]; v.y = acc[i][1]; v.z = acc[i][2]; v.w = acc[i][3];
                ((float4*)(ks + (og*7 + i)*128))[pg] = v;
            }
        }
    }
    __syncthreads();

    // ---- involution ----
    const int wg = t & 31;
    const int cl = t >> 5;
    const int pp = pix0 + wg*4;
    const int h  = pp / WW;
    const int w0 = pp - h*WW;

    float acc[8][4];
    #pragma unroll
    for (int cc = 0; cc < 8; cc++)
        #pragma unroll
        for (int j = 0; j < 4; j++) acc[cc][j] = 0.f;

    {
        const float* xbase = x + ((size_t)b*CH + cl*8)*HWS;
        const float4 zero4 = make_float4(0.f, 0.f, 0.f, 0.f);
        #pragma unroll
        for (int kh = 0; kh < 7; kh++) {
            const int row = h + kh - 3;
            if (row < 0 || row >= HH) continue;
            float4 kv[7];
            #pragma unroll
            for (int kw = 0; kw < 7; kw++)
                kv[kw] = ((const float4*)(ks + (kh*7 + kw)*128))[wg];
            const float* xrow = xbase + (size_t)row*WW;
            #pragma unroll
            for (int cc = 0; cc < 8; cc++) {
                const float* xc = xrow + (size_t)cc*HWS;
                float4 v1 = *(const float4*)(xc + w0);
                float4 v0 = (w0 >= 4)   ? *(const float4*)(xc + w0 - 4) : zero4;
                float4 v2 = (w0 <= 104) ? *(const float4*)(xc + w0 + 4) : zero4;
                float xr[10] = {v0.y, v0.z, v0.w, v1.x, v1.y, v1.z, v1.w, v2.x, v2.y, v2.z};
                #pragma unroll
                for (int kw = 0; kw < 7; kw++) {
                    acc[cc][0] = fmaf(xr[0 + kw], kv[kw].x, acc[cc][0]);
                    acc[cc][1] = fmaf(xr[1 + kw], kv[kw].y, acc[cc][1]);
                    acc[cc][2] = fmaf(xr[2 + kw], kv[kw].z, acc[cc][2]);
                    acc[cc][3] = fmaf(xr[3 + kw], kv[kw].w, acc[cc][3]);
                }
            }
        }
    }

    float* ob = g_out0 + ((size_t)b*CH + cl*8)*HWS + pp;
    #pragma unroll
    for (int cc = 0; cc < 8; cc++) {
        float4 v; v.x = acc[cc][0]; v.y = acc[cc][1]; v.z = acc[cc][2]; v.w = acc[cc][3];
        *((float4*)(ob + (size_t)cc*HWS)) = v;
        float s = v.x + v.y + v.z + v.w;
        float q = v.x*v.x + v.y*v.y + v.z*v.z + v.w*v.w;
        atomicAdd(&sred[cl*8 + cc], s);
        atomicAdd(&sred[CH + cl*8 + cc], q);
    }
    __syncthreads();
    if (t < 128) atomicAdd(&g_stats2[t], sred[t]);
}

// ---------------------------------------------------------------- K3: bn2 finalize + affine + PReLU
// One block per (b,c) image-channel. Block 0 zeroes g_stats1 for the next replay.
__global__ __launch_bounds__(256) void k_apply(const float* __restrict__ gamma,
                                               const float* __restrict__ beta,
                                               const float* __restrict__ alpha,
                                               float* __restrict__ out) {
    __shared__ float s_p[3];
    const int t = threadIdx.x;
    const int bc = blockIdx.x;
    const int c = bc & (CH-1);

    if (t == 0) {
        const float n = (float)NPIX;
        float mean = g_stats2[c] / n;
        float var  = g_stats2[CH + c] / n - mean*mean;
        float sc = gamma[c] * rsqrtf(var + 1e-3f);
        s_p[0] = sc;
        s_p[1] = beta[c] - mean*sc;
        s_p[2] = alpha[c];
    }
    if (bc == 0 && t < 2*CH) g_stats1[t] = 0.f;
    __syncthreads();

    const float sc = s_p[0], sh = s_p[1], al = s_p[2];
    const float4* src = (const float4*)(g_out0 + (size_t)bc*HWS);
    float4* dst = (float4*)(out + (size_t)bc*HWS);
    #pragma unroll 4
    for (int i = t; i < HWS/4; i += 256) {
        float4 v = src[i];
        float u;
        u = fmaf(v.x, sc, sh); v.x = u > 0.f ? u : al*u;
        u = fmaf(v.y, sc, sh); v.y = u > 0.f ? u : al*u;
        u = fmaf(v.z, sc, sh); v.z = u > 0.f ? u : al*u;
        u = fmaf(v.w, sc, sh); v.w = u > 0.f ? u : al*u;
        dst[i] = v;
    }
}

// ----------------------------------------------------------------
extern "C" void kernel_launch(void* const* d_in, const int* in_sizes, int n_in,
                              void* d_out, int out_size) {
    const float* x     = (const float*)d_in[0];
    const float* wred  = (const float*)d_in[1];
    const float* g1    = (const float*)d_in[2];
    const float* b1    = (const float*)d_in[3];
    const float* wspan = (const float*)d_in[4];
    const float* g2    = (const float*)d_in[5];
    const float* b2    = (const float*)d_in[6];
    const float* alpha = (const float*)d_in[7];
    float* out = (float*)d_out;

    const int smem_main = (KK*CH + CH*128 + KK*128 + 128 + 128) * sizeof(float); // 71424 B
    cudaFuncSetAttribute(k_main, cudaFuncAttributeMaxDynamicSharedMemorySize, smem_main);

    k_reduce<<<dim3(HWS/128, BB), 256>>>(x, wred);
    k_main  <<<dim3(HWS/128, BB), 256, smem_main>>>(x, wspan, g1, b1);
    k_apply <<<BB*CH, 256>>>(g2, b2, alpha, out);
}

// round 9
// speedup vs baseline: 1.1566x; 1.1566x over previous
#include <cuda_runtime.h>
#include <cuda_bf16.h>
#include <cstdint>

#define CH   64
#define HH   112
#define WW   112
#define HWS  12544
#define BB   4
#define KK   49
#define NPIX (BB*HWS)

// Scratch (device globals — no allocation allowed). Zero-initialized at load.
__device__ __align__(16) float g_y0  [BB*CH*HWS];   // reduce output (pre-BN1)
__device__ __align__(16) float g_out0[BB*CH*HWS];   // involution output (pre-BN2)
__device__ float g_stats1[2*CH];
__device__ float g_stats2[2*CH];

// ---- packed bf16 helpers ----
__device__ __forceinline__ uint32_t pack_bf2(float lo, float hi) {
    __nv_bfloat162 p = __floats2bfloat162_rn(lo, hi);   // .x=lo(bits15:0), .y=hi(bits31:16)
    uint32_t u; *(__nv_bfloat162*)&u = p; return u;
}
// exact f32 values of the packed bf16 pair
__device__ __forceinline__ float bf2_lo(uint32_t u) { return __uint_as_float(u << 16); }
__device__ __forceinline__ float bf2_hi(uint32_t u) { return __uint_as_float(u & 0xFFFF0000u); }

__device__ __forceinline__ void mma_bf16(float c[4], uint32_t a0, uint32_t a1,
                                         uint32_t a2, uint32_t a3,
                                         uint32_t b0, uint32_t b1) {
    asm volatile(
        "mma.sync.aligned.m16n8k16.row.col.f32.bf16.bf16.f32 "
        "{%0,%1,%2,%3}, {%4,%5,%6,%7}, {%8,%9}, {%0,%1,%2,%3};"
        : "+f"(c[0]), "+f"(c[1]), "+f"(c[2]), "+f"(c[3])
        : "r"(a0), "r"(a1), "r"(a2), "r"(a3), "r"(b0), "r"(b1));
}

// smem layout for k_reduce (u32 word offsets)
#define APAD 37                      // A row pad (u32 words): conflict-free frag loads
#define BPAD 33                      // B row pad
#define OFF_AHI 0
#define OFF_ALO (128*APAD)           // 4736
#define OFF_BHI (2*128*APAD)         // 9472
#define OFF_BLO (OFF_BHI + 64*BPAD)  // 11584
#define RED_WORDS (OFF_BLO + 64*BPAD)// 13696 words = 54784 B
#define RED_SMEM (RED_WORDS*4)

// ---------------------------------------------------------------- K1: reduce GEMM (HMMA bf16x3) + stats1
// D[pix 128][out 64] = X[128,64] · Wred[64,64]^T, per 128-pixel block.
__global__ __launch_bounds__(256) void k_reduce(const float* __restrict__ x,
                                                const float* __restrict__ wred) {
    extern __shared__ __align__(16) uint32_t smw[];
    uint32_t* ahix = smw + OFF_AHI;   // [128 pix][37]: word j = bf16(ch 2j, 2j+1) hi
    uint32_t* alox = smw + OFF_ALO;
    uint32_t* whix = smw + OFF_BHI;   // [64 out][33]
    uint32_t* wlox = smw + OFF_BLO;

    const int t = threadIdx.x;
    const int wid = t >> 5, lid = t & 31;
    const int b = blockIdx.y;
    const int pix0 = blockIdx.x * 128;

    if (blockIdx.x == 0 && b == 0 && t < 2*CH) g_stats2[t] = 0.f;

    // ---- stage A (x tile) as packed hi/lo bf16 pairs ----
    const float* xb = x + (size_t)b*CH*HWS + pix0;
    #pragma unroll
    for (int l = t; l < 32*128; l += 256) {
        int c2 = l >> 7, p = l & 127;
        float v0 = xb[(size_t)(2*c2)*HWS + p];
        float v1 = xb[(size_t)(2*c2+1)*HWS + p];
        uint32_t hp = pack_bf2(v0, v1);
        uint32_t lp = pack_bf2(v0 - bf2_lo(hp), v1 - bf2_hi(hp));
        ahix[p*APAD + c2] = hp;
        alox[p*APAD + c2] = lp;
    }
    // ---- stage B (wred) ----
    #pragma unroll
    for (int l = t; l < 32*64; l += 256) {
        int c2 = l & 31, n = l >> 5;
        float v0 = wred[n*CH + 2*c2];
        float v1 = wred[n*CH + 2*c2 + 1];
        uint32_t hp = pack_bf2(v0, v1);
        uint32_t lp = pack_bf2(v0 - bf2_lo(hp), v1 - bf2_hi(hp));
        whix[n*BPAD + c2] = hp;
        wlox[n*BPAD + c2] = lp;
    }
    __syncthreads();

    // ---- HMMA mainloop: warp w -> pixels w*16..w*16+15, all 64 outputs ----
    const int gid = lid >> 2, tig = lid & 3;
    const int p0 = wid*16 + gid;
    float acc[8][4];
    #pragma unroll
    for (int i = 0; i < 8; i++)
        #pragma unroll
        for (int j = 0; j < 4; j++) acc[i][j] = 0.f;

    #pragma unroll
    for (int ks = 0; ks < 4; ks++) {
        const int j0 = tig + ks*8, j1 = tig + 4 + ks*8;
        uint32_t ah0 = ahix[p0*APAD + j0],     ah1 = ahix[(p0+8)*APAD + j0];
        uint32_t ah2 = ahix[p0*APAD + j1],     ah3 = ahix[(p0+8)*APAD + j1];
        uint32_t al0 = alox[p0*APAD + j0],     al1 = alox[(p0+8)*APAD + j0];
        uint32_t al2 = alox[p0*APAD + j1],     al3 = alox[(p0+8)*APAD + j1];
        #pragma unroll
        for (int nt = 0; nt < 8; nt++) {
            const int n = nt*8 + gid;
            uint32_t bh0 = whix[n*BPAD + j0], bh1 = whix[n*BPAD + j1];
            uint32_t bl0 = wlox[n*BPAD + j0], bl1 = wlox[n*BPAD + j1];
            mma_bf16(acc[nt], ah0, ah1, ah2, ah3, bh0, bh1);
            mma_bf16(acc[nt], ah0, ah1, ah2, ah3, bl0, bl1);
            mma_bf16(acc[nt], al0, al1, al2, al3, bh0, bh1);
        }
    }
    __syncthreads();   // tiles dead; reuse smem for transpose pad

    // ---- fragments -> pad [64 o][129]: conflict-free by construction ----
    float* pad = (float*)smw;
    #pragma unroll
    for (int nt = 0; nt < 8; nt++) {
        const int o = nt*8 + 2*tig;
        pad[o*129 + p0]           = acc[nt][0];
        pad[(o+1)*129 + p0]       = acc[nt][1];
        pad[o*129 + p0 + 8]       = acc[nt][2];
        pad[(o+1)*129 + p0 + 8]   = acc[nt][3];
    }
    __syncthreads();

    // ---- coalesced global write ----
    float* y0b = g_y0 + (size_t)b*CH*HWS + pix0;
    #pragma unroll
    for (int l = t; l < CH*128; l += 256) {
        int o = l >> 7, p = l & 127;
        y0b[(size_t)o*HWS + p] = pad[o*129 + p];
    }
    // ---- stats1: 4 partials per channel ----
    {
        const int o = t & 63, quarter = t >> 6;
        float s = 0.f, q = 0.f;
        #pragma unroll 8
        for (int i = 0; i < 32; i++) {
            float v = pad[o*129 + quarter*32 + i];
            s += v; q = fmaf(v, v, q);
        }
        atomicAdd(&g_stats1[o], s);
        atomicAdd(&g_stats1[CH + o], q);
    }
}

// ---------------------------------------------------------------- K2: bn1 + span GEMM + involution + stats2
// (unchanged — proven configuration)
__global__ __launch_bounds__(256, 3) void k_main(const float* __restrict__ x,
                                                 const float* __restrict__ wspan,
                                                 const float* __restrict__ g1,
                                                 const float* __restrict__ b1) {
    extern __shared__ __align__(16) float sm[];
    float* ws   = sm;                       // [49*64]  span weights
    float* ys   = ws + KK*CH;               // [64*128] bn1-relu'd y0 tile
    float* ks   = ys + CH*128;              // [49*128] per-pixel kernels
    float* bn   = ks + KK*128;              // [128]    bn1 scale/shift
    float* sred = bn + 128;                 // [128]    stats2 partial

    const int t = threadIdx.x;
    const int b = blockIdx.y;
    const int pix0 = blockIdx.x * 128;

    if (t < CH) {
        const float n = (float)NPIX;
        float mean = g_stats1[t] / n;
        float var  = g_stats1[CH + t] / n - mean*mean;
        float sc = g1[t] * rsqrtf(var + 1e-5f);
        bn[t]      = sc;
        bn[CH + t] = b1[t] - mean*sc;
    }
    if (t < 128) sred[t] = 0.f;
    for (int l = t; l < KK*CH; l += 256) ws[l] = wspan[l];
    __syncthreads();

    const float* y0b = g_y0 + (size_t)b*CH*HWS + pix0;
    for (int l = t; l < CH*128; l += 256) {
        int c = l >> 7, p = l & 127;
        float v = y0b[(size_t)c*HWS + p];
        ys[l] = fmaxf(fmaf(v, bn[c], bn[CH + c]), 0.f);
    }
    __syncthreads();

    {
        const int og = t >> 5;
        const int pg = t & 31;
        if (og < 7) {
            float acc[7][4];
            #pragma unroll
            for (int i = 0; i < 7; i++)
                #pragma unroll
                for (int j = 0; j < 4; j++) acc[i][j] = 0.f;
            #pragma unroll 4
            for (int c = 0; c < CH; c++) {
                float4 xv = ((const float4*)(ys + c*128))[pg];
                #pragma unroll
                for (int i = 0; i < 7; i++) {
                    float w = ws[(og*7 + i)*CH + c];
                    acc[i][0] = fmaf(w, xv.x, acc[i][0]);
                    acc[i][1] = fmaf(w, xv.y, acc[i][1]);
                    acc[i][2] = fmaf(w, xv.z, acc[i][2]);
                    acc[i][3] = fmaf(w, xv.w, acc[i][3]);
                }
            }
            #pragma unroll
            for (int i = 0; i < 7; i++) {
                float4 v; v.x = acc[i][0]; v.y = acc[i][1]; v.z = acc[i][2]; v.w = acc[i][3];
                ((float4*)(ks + (og*7 + i)*128))[pg] = v;
            }
        }
    }
    __syncthreads();

    const int wg = t & 31;
    const int cl = t >> 5;
    const int pp = pix0 + wg*4;
    const int h  = pp / WW;
    const int w0 = pp - h*WW;

    float acc[8][4];
    #pragma unroll
    for (int cc = 0; cc < 8; cc++)
        #pragma unroll
        for (int j = 0; j < 4; j++) acc[cc][j] = 0.f;

    {
        const float* xbase = x + ((size_t)b*CH + cl*8)*HWS;
        const float4 zero4 = make_float4(0.f, 0.f, 0.f, 0.f);
        #pragma unroll
        for (int kh = 0; kh < 7; kh++) {
            const int row = h + kh - 3;
            if (row < 0 || row >= HH) continue;
            float4 kv[7];
            #pragma unroll
            for (int kw = 0; kw < 7; kw++)
                kv[kw] = ((const float4*)(ks + (kh*7 + kw)*128))[wg];
            const float* xrow = xbase + (size_t)row*WW;
            #pragma unroll
            for (int cc = 0; cc < 8; cc++) {
                const float* xc = xrow + (size_t)cc*HWS;
                float4 v1 = *(const float4*)(xc + w0);
                float4 v0 = (w0 >= 4)   ? *(const float4*)(xc + w0 - 4) : zero4;
                float4 v2 = (w0 <= 104) ? *(const float4*)(xc + w0 + 4) : zero4;
                float xr[10] = {v0.y, v0.z, v0.w, v1.x, v1.y, v1.z, v1.w, v2.x, v2.y, v2.z};
                #pragma unroll
                for (int kw = 0; kw < 7; kw++) {
                    acc[cc][0] = fmaf(xr[0 + kw], kv[kw].x, acc[cc][0]);
                    acc[cc][1] = fmaf(xr[1 + kw], kv[kw].y, acc[cc][1]);
                    acc[cc][2] = fmaf(xr[2 + kw], kv[kw].z, acc[cc][2]);
                    acc[cc][3] = fmaf(xr[3 + kw], kv[kw].w, acc[cc][3]);
                }
            }
        }
    }

    float* ob = g_out0 + ((size_t)b*CH + cl*8)*HWS + pp;
    #pragma unroll
    for (int cc = 0; cc < 8; cc++) {
        float4 v; v.x = acc[cc][0]; v.y = acc[cc][1]; v.z = acc[cc][2]; v.w = acc[cc][3];
        *((float4*)(ob + (size_t)cc*HWS)) = v;
        float s = v.x + v.y + v.z + v.w;
        float q = v.x*v.x + v.y*v.y + v.z*v.z + v.w*v.w;
        atomicAdd(&sred[cl*8 + cc], s);
        atomicAdd(&sred[CH + cl*8 + cc], q);
    }
    __syncthreads();
    if (t < 128) atomicAdd(&g_stats2[t], sred[t]);
}

// ---------------------------------------------------------------- K3: bn2 finalize + affine + PReLU
__global__ __launch_bounds__(256) void k_apply(const float* __restrict__ gamma,
                                               const float* __restrict__ beta,
                                               const float* __restrict__ alpha,
                                               float* __restrict__ out) {
    __shared__ float s_p[3];
    const int t = threadIdx.x;
    const int bc = blockIdx.x;
    const int c = bc & (CH-1);

    if (t == 0) {
        const float n = (float)NPIX;
        float mean = g_stats2[c] / n;
        float var  = g_stats2[CH + c] / n - mean*mean;
        float sc = gamma[c] * rsqrtf(var + 1e-3f);
        s_p[0] = sc;
        s_p[1] = beta[c] - mean*sc;
        s_p[2] = alpha[c];
    }
    if (bc == 0 && t < 2*CH) g_stats1[t] = 0.f;
    __syncthreads();

    const float sc = s_p[0], sh = s_p[1], al = s_p[2];
    const float4* src = (const float4*)(g_out0 + (size_t)bc*HWS);
    float4* dst = (float4*)(out + (size_t)bc*HWS);
    #pragma unroll 4
    for (int i = t; i < HWS/4; i += 256) {
        float4 v = src[i];
        float u;
        u = fmaf(v.x, sc, sh); v.x = u > 0.f ? u : al*u;
        u = fmaf(v.y, sc, sh); v.y = u > 0.f ? u : al*u;
        u = fmaf(v.z, sc, sh); v.z = u > 0.f ? u : al*u;
        u = fmaf(v.w, sc, sh); v.w = u > 0.f ? u : al*u;
        dst[i] = v;
    }
}

// ----------------------------------------------------------------
extern "C" void kernel_launch(void* const* d_in, const int* in_sizes, int n_in,
                              void* d_out, int out_size) {
    const float* x     = (const float*)d_in[0];
    const float* wred  = (const float*)d_in[1];
    const float* g1    = (const float*)d_in[2];
    const float* b1    = (const float*)d_in[3];
    const float* wspan = (const float*)d_in[4];
    const float* g2    = (const float*)d_in[5];
    const float* b2    = (const float*)d_in[6];
    const float* alpha = (const float*)d_in[7];
    float* out = (float*)d_out;

    const int smem_main = (KK*CH + CH*128 + KK*128 + 128 + 128) * sizeof(float); // 71424 B
    cudaFuncSetAttribute(k_reduce, cudaFuncAttributeMaxDynamicSharedMemorySize, RED_SMEM);
    cudaFuncSetAttribute(k_main,   cudaFuncAttributeMaxDynamicSharedMemorySize, smem_main);

    k_reduce<<<dim3(HWS/128, BB), 256, RED_SMEM>>>(x, wred);
    k_main  <<<dim3(HWS/128, BB), 256, smem_main>>>(x, wspan, g1, b1);
    k_apply <<<BB*CH, 256>>>(g2, b2, alpha, out);
}